// round 5
// baseline (speedup 1.0000x reference)
#include <cuda_runtime.h>
#include <cuda_bf16.h>
#include <cstdint>
#include <math.h>

// ---------------------------------------------------------------------------
// Problem constants
// ---------------------------------------------------------------------------
constexpr int Bb = 2;
constexpr int Ss = 2048;
constexpr int Dd = 1024;
constexpr int Hh = 16;
constexpr int DK = 64;
constexpr int Mrows = Bb * Ss;           // 4096
constexpr float SCALE = 0.125f;          // 1/sqrt(64)

// ---------------------------------------------------------------------------
// Scratch (device globals)
// ---------------------------------------------------------------------------
__device__ __nv_bfloat16 g_qhi[(size_t)Mrows * Dd], g_qlo[(size_t)Mrows * Dd];
__device__ __nv_bfloat16 g_khi[(size_t)Mrows * Dd], g_klo[(size_t)Mrows * Dd];
__device__ __nv_bfloat16 g_vhi[(size_t)Mrows * Dd], g_vlo[(size_t)Mrows * Dd];
__device__ __nv_bfloat16 g_ohi[(size_t)Mrows * Dd], g_olo[(size_t)Mrows * Dd];
__device__ __nv_bfloat16 g_whi[4][(size_t)Dd * Dd], g_wlo[4][(size_t)Dd * Dd];

// split-head projected tensors [bh=32][S=2048][DK=64], bf16 hi/lo
__device__ __nv_bfloat16 g_Qh[(size_t)32 * Ss * DK], g_Ql[(size_t)32 * Ss * DK];
__device__ __nv_bfloat16 g_Kh[(size_t)32 * Ss * DK], g_Kl[(size_t)32 * Ss * DK];
__device__ __nv_bfloat16 g_Vh[(size_t)32 * Ss * DK], g_Vl[(size_t)32 * Ss * DK];

// ---------------------------------------------------------------------------
// mma.sync / ldmatrix / cp.async helpers
// ---------------------------------------------------------------------------
__device__ __forceinline__ uint32_t smem_u32(const void* p) {
    uint32_t a;
    asm("{ .reg .u64 t; cvta.to.shared.u64 t, %1; cvt.u32.u64 %0, t; }"
        : "=r"(a) : "l"(p));
    return a;
}
__device__ __forceinline__ void ldm_x4(uint32_t* r, uint32_t addr) {
    asm volatile("ldmatrix.sync.aligned.m8n8.x4.shared.b16 {%0,%1,%2,%3}, [%4];"
                 : "=r"(r[0]), "=r"(r[1]), "=r"(r[2]), "=r"(r[3]) : "r"(addr));
}
__device__ __forceinline__ void ldm_x4_t(uint32_t* r, uint32_t addr) {
    asm volatile("ldmatrix.sync.aligned.m8n8.x4.trans.shared.b16 {%0,%1,%2,%3}, [%4];"
                 : "=r"(r[0]), "=r"(r[1]), "=r"(r[2]), "=r"(r[3]) : "r"(addr));
}
__device__ __forceinline__ void mma16816(float* c, const uint32_t* a,
                                         uint32_t b0, uint32_t b1) {
    asm volatile(
        "mma.sync.aligned.m16n8k16.row.col.f32.bf16.bf16.f32 "
        "{%0,%1,%2,%3}, {%4,%5,%6,%7}, {%8,%9}, {%0,%1,%2,%3};"
        : "+f"(c[0]), "+f"(c[1]), "+f"(c[2]), "+f"(c[3])
        : "r"(a[0]), "r"(a[1]), "r"(a[2]), "r"(a[3]), "r"(b0), "r"(b1));
}
__device__ __forceinline__ void cp16(uint32_t dst, const void* src) {
    asm volatile("cp.async.cg.shared.global [%0], [%1], 16;"
                 :: "r"(dst), "l"(src) : "memory");
}
__device__ __forceinline__ void cp_commit() {
    asm volatile("cp.async.commit_group;" ::: "memory");
}
template <int N>
__device__ __forceinline__ void cp_wait() {
    asm volatile("cp.async.wait_group %0;" :: "n"(N) : "memory");
}

template <int ROWB>
__device__ __forceinline__ uint32_t fragA(uint32_t base, int row0, int kb0, int lane) {
    int r = row0 + ((lane >> 3) & 1) * 8 + (lane & 7);
    int kb = kb0 + (lane >> 4) * 16;
    return base + r * ROWB + kb;
}
template <int ROWB>
__device__ __forceinline__ uint32_t fragT(uint32_t base, int k0, int nb0, int lane) {
    int r = k0 + ((lane >> 4) & 1) * 8 + (lane & 7);
    int cb = nb0 + ((lane >> 3) & 1) * 16;
    return base + r * ROWB + cb;
}

__device__ __forceinline__ uint32_t packbf2(float lo, float hi) {
    __nv_bfloat162 t = __floats2bfloat162_rn(lo, hi);
    return *(uint32_t*)&t;
}

// ---------------------------------------------------------------------------
// fp32 -> bf16 hi/lo split, row-major
// ---------------------------------------------------------------------------
__global__ __launch_bounds__(256)
void cvt_split(const float* __restrict__ x, __nv_bfloat16* __restrict__ hi,
               __nv_bfloat16* __restrict__ lo) {
    int i = (blockIdx.x * 256 + threadIdx.x) * 4;
    float4 v = *(const float4*)(x + i);
    float vv[4] = {v.x, v.y, v.z, v.w};
#pragma unroll
    for (int j = 0; j < 4; j++) {
        __nv_bfloat16 h = __float2bfloat16(vv[j]);
        hi[i + j] = h;
        lo[i + j] = __float2bfloat16(vv[j] - __bfloat162float(h));
    }
}

// fp32 W[K,N] -> bf16 hi/lo TRANSPOSED [N,K]
__global__ __launch_bounds__(256)
void cvt_splitT(const float* __restrict__ W, __nv_bfloat16* __restrict__ hiT,
                __nv_bfloat16* __restrict__ loT) {
    __shared__ float t[32][33];
    int tx = threadIdx.x, ty = threadIdx.y;
    int n0 = blockIdx.x * 32, k0 = blockIdx.y * 32;
#pragma unroll
    for (int r = 0; r < 4; r++)
        t[ty + r * 8][tx] = W[(size_t)(k0 + ty + r * 8) * Dd + n0 + tx];
    __syncthreads();
#pragma unroll
    for (int r = 0; r < 4; r++) {
        int n = n0 + ty + r * 8;
        int k = k0 + tx;
        float x = t[tx][ty + r * 8];
        __nv_bfloat16 h = __float2bfloat16(x);
        hiT[(size_t)n * Dd + k] = h;
        loT[(size_t)n * Dd + k] = __float2bfloat16(x - __bfloat162float(h));
    }
}

// ---------------------------------------------------------------------------
// bf16-split tensor-core GEMM (unchanged from R4)
// ---------------------------------------------------------------------------
constexpr int ROW_B = 80;
constexpr int ARR_B = 128 * ROW_B;
constexpr int BUF_B = 4 * ARR_B;
constexpr int GEMM_SMEM_BYTES = 2 * BUF_B;  // 81920

template <int MODE>
__global__ __launch_bounds__(256, 1)
void gemm_bf16split(const __nv_bfloat16* __restrict__ Ahi,
                    const __nv_bfloat16* __restrict__ Alo,
                    const __nv_bfloat16* __restrict__ Bhi,
                    const __nv_bfloat16* __restrict__ Blo,
                    float* __restrict__ C,
                    __nv_bfloat16* __restrict__ Chi,
                    __nv_bfloat16* __restrict__ Clo) {
    extern __shared__ char smem[];
    const uint32_t sbase = smem_u32(smem);
    const int tid = threadIdx.x;
    const int lane = tid & 31;
    const int wid = tid >> 5;
    const int wm = wid >> 2;
    const int wn = wid & 3;
    const int bm = blockIdx.y * 128;
    const int bn = blockIdx.x * 128;

    const __nv_bfloat16* srcs[4] = {Ahi, Alo, Bhi, Blo};

    auto load_chunk = [&](int c, int b) {
        const int k0 = c * 32;
        const uint32_t dst0 = sbase + b * BUF_B;
        const int row = tid >> 1;
#pragma unroll
        for (int a4 = 0; a4 < 4; a4++) {
            const __nv_bfloat16* src = srcs[a4];
            const int rbase = (a4 < 2) ? bm : bn;
            const __nv_bfloat16* gsrc = src + (size_t)(rbase + row) * Dd + k0;
#pragma unroll
            for (int j = 0; j < 2; j++) {
                int cch = (tid & 1) * 2 + j;
                cp16(dst0 + a4 * ARR_B + row * ROW_B + cch * 16, gsrc + cch * 8);
            }
        }
        cp_commit();
    };

    float acc[4][4][4];
#pragma unroll
    for (int i = 0; i < 4; i++)
#pragma unroll
        for (int j = 0; j < 4; j++)
#pragma unroll
            for (int r = 0; r < 4; r++) acc[i][j][r] = 0.0f;

    auto compute = [&](int b) {
        const uint32_t base = sbase + b * BUF_B;
        const uint32_t aHiB = base + 0 * ARR_B;
        const uint32_t aLoB = base + 1 * ARR_B;
        const uint32_t bHiB = base + 2 * ARR_B;
        const uint32_t bLoB = base + 3 * ARR_B;
#pragma unroll
        for (int s = 0; s < 2; s++) {
            const int kb = s * 32;
            uint32_t ahi[4][4], alo[4][4];
#pragma unroll
            for (int i = 0; i < 4; i++) {
                ldm_x4(ahi[i], fragA<ROW_B>(aHiB, wm * 64 + i * 16, kb, lane));
                ldm_x4(alo[i], fragA<ROW_B>(aLoB, wm * 64 + i * 16, kb, lane));
            }
#pragma unroll
            for (int nb = 0; nb < 2; nb++) {
                uint32_t bh[4], bl[4];
                ldm_x4(bh, fragA<ROW_B>(bHiB, wn * 32 + nb * 16, kb, lane));
                ldm_x4(bl, fragA<ROW_B>(bLoB, wn * 32 + nb * 16, kb, lane));
#pragma unroll
                for (int i = 0; i < 4; i++) {
                    mma16816(acc[i][nb * 2 + 0], ahi[i], bh[0], bh[2]);
                    mma16816(acc[i][nb * 2 + 1], ahi[i], bh[1], bh[3]);
                    mma16816(acc[i][nb * 2 + 0], ahi[i], bl[0], bl[2]);
                    mma16816(acc[i][nb * 2 + 1], ahi[i], bl[1], bl[3]);
                    mma16816(acc[i][nb * 2 + 0], alo[i], bh[0], bh[2]);
                    mma16816(acc[i][nb * 2 + 1], alo[i], bh[1], bh[3]);
                }
            }
        }
    };

    constexpr int NCHUNK = Dd / 32;
    load_chunk(0, 0);
    for (int c = 0; c < NCHUNK; c++) {
        if (c + 1 < NCHUNK) {
            load_chunk(c + 1, (c + 1) & 1);
            cp_wait<1>();
        } else {
            cp_wait<0>();
        }
        __syncthreads();
        compute(c & 1);
        __syncthreads();
    }

    const int g = lane >> 2;
    const int tg = lane & 3;
#pragma unroll
    for (int i = 0; i < 4; i++) {
        int r0 = bm + wm * 64 + i * 16 + g;
#pragma unroll
        for (int j = 0; j < 4; j++) {
            int col = bn + wn * 32 + j * 8 + tg * 2;
            if (MODE == 0) {
                *(float2*)(C + (size_t)r0 * Dd + col) =
                    make_float2(acc[i][j][0], acc[i][j][1]);
                *(float2*)(C + (size_t)(r0 + 8) * Dd + col) =
                    make_float2(acc[i][j][2], acc[i][j][3]);
            } else {
                int h = col >> 6, dk = col & 63;
#pragma unroll
                for (int half = 0; half < 2; half++) {
                    int r = r0 + half * 8;
                    int b_ = r >> 11, s = r & 2047;
                    size_t addr = (((size_t)(b_ * Hh + h)) * Ss + s) * DK + dk;
                    float x = acc[i][j][half * 2], y = acc[i][j][half * 2 + 1];
                    __nv_bfloat16 hx = __float2bfloat16(x);
                    __nv_bfloat16 hy = __float2bfloat16(y);
                    *(uint32_t*)(Chi + addr) =
                        packbf2(__bfloat162float(hx), __bfloat162float(hy));
                    *(uint32_t*)(Clo + addr) =
                        packbf2(x - __bfloat162float(hx), y - __bfloat162float(hy));
                }
            }
        }
    }
}

// ---------------------------------------------------------------------------
// Tensor-core flash attention, 64-key tiles, 2 CTAs/SM.
// CTA = (head bh, 128 q rows). 8 warps x 16 rows. Q frags re-read from smem
// each tile (register budget <= 128 for occupancy 2).
// ---------------------------------------------------------------------------
constexpr int AROW = 144;                        // 64 bf16 = 128B + 16 pad
constexpr int Q_TILE_B = 128 * AROW;             // 18432 (128 q rows)
constexpr int KV_TILE_B = 64 * AROW;             // 9216  (64 keys)
constexpr int ATT_BUF_B = 4 * KV_TILE_B;         // Khi,Klo,Vhi,Vlo = 36864
constexpr int ATT_SMEM = 2 * Q_TILE_B + 2 * ATT_BUF_B;  // 110592

__global__ __launch_bounds__(256, 2)
void attn_mma() {
    extern __shared__ char smem[];
    const uint32_t sb = smem_u32(smem);
    const int tid = threadIdx.x;
    const int lane = tid & 31;
    const int w = tid >> 5;
    const int bh = blockIdx.y;
    const int qt = blockIdx.x;
    const int b = bh >> 4, h = bh & 15;

    const __nv_bfloat16* Qhg = g_Qh + (size_t)bh * Ss * DK + qt * 128 * DK;
    const __nv_bfloat16* Qlg = g_Ql + (size_t)bh * Ss * DK + qt * 128 * DK;
    const __nv_bfloat16* Khg = g_Kh + (size_t)bh * Ss * DK;
    const __nv_bfloat16* Klg = g_Kl + (size_t)bh * Ss * DK;
    const __nv_bfloat16* Vhg = g_Vh + (size_t)bh * Ss * DK;
    const __nv_bfloat16* Vlg = g_Vl + (size_t)bh * Ss * DK;

    const uint32_t sQh = sb, sQl = sb + Q_TILE_B;

    // load 64-key K/V hi/lo tile into buffer buf: 8 cp16 per thread
    auto load_kv = [&](int kt, int buf) {
        const uint32_t base = sb + 2 * Q_TILE_B + buf * ATT_BUF_B;
        const __nv_bfloat16* gk[4] = {Khg, Klg, Vhg, Vlg};
#pragma unroll
        for (int a4 = 0; a4 < 4; a4++) {
            const __nv_bfloat16* src = gk[a4] + (size_t)kt * 64 * DK;
#pragma unroll
            for (int p = 0; p < 2; p++) {
                int idx = tid + p * 256;      // 0..511
                int r = idx >> 3, c = idx & 7;
                cp16(base + a4 * KV_TILE_B + r * AROW + c * 16, src + r * DK + c * 8);
            }
        }
        cp_commit();
    };

    // Q tiles (hi/lo)
#pragma unroll
    for (int p = 0; p < 4; p++) {
        int idx = tid + p * 256;
        int r = idx >> 3, c = idx & 7;
        cp16(sQh + r * AROW + c * 16, Qhg + r * DK + c * 8);
        cp16(sQl + r * AROW + c * 16, Qlg + r * DK + c * 8);
    }
    load_kv(0, 0);
    cp_wait<0>();
    __syncthreads();

    float m0 = -1e30f, m1 = -1e30f, l0 = 0.0f, l1 = 0.0f;
    float Oacc[8][4];
#pragma unroll
    for (int j = 0; j < 8; j++)
#pragma unroll
        for (int r = 0; r < 4; r++) Oacc[j][r] = 0.0f;

    constexpr int NT = Ss / 64;   // 32
    for (int kt = 0; kt < NT; kt++) {
        if (kt + 1 < NT) {
            load_kv(kt + 1, (kt + 1) & 1);
            cp_wait<1>();
        } else {
            cp_wait<0>();
        }
        __syncthreads();

        const uint32_t base = sb + 2 * Q_TILE_B + (kt & 1) * ATT_BUF_B;
        const uint32_t kHi = base, kLo = base + KV_TILE_B;
        const uint32_t vHi = base + 2 * KV_TILE_B, vLo = base + 3 * KV_TILE_B;

        // ---- S = Q K^T (fp32 acc), 16x64 per warp
        float sfr[8][4];
#pragma unroll
        for (int j = 0; j < 8; j++)
#pragma unroll
            for (int r = 0; r < 4; r++) sfr[j][r] = 0.0f;

#pragma unroll
        for (int s = 0; s < 4; s++) {          // dk k16 steps
            const int kb = s * 32;
            uint32_t qh[4], ql[4];
            ldm_x4(qh, fragA<AROW>(sQh, w * 16, kb, lane));
            ldm_x4(ql, fragA<AROW>(sQl, w * 16, kb, lane));
#pragma unroll
            for (int nb = 0; nb < 4; nb++) {   // key n16 blocks
                uint32_t bh4[4], bl4[4];
                ldm_x4(bh4, fragA<AROW>(kHi, nb * 16, kb, lane));
                ldm_x4(bl4, fragA<AROW>(kLo, nb * 16, kb, lane));
                mma16816(sfr[nb * 2 + 0], qh, bh4[0], bh4[2]);
                mma16816(sfr[nb * 2 + 1], qh, bh4[1], bh4[3]);
                mma16816(sfr[nb * 2 + 0], qh, bl4[0], bl4[2]);
                mma16816(sfr[nb * 2 + 1], qh, bl4[1], bl4[3]);
                mma16816(sfr[nb * 2 + 0], ql, bh4[0], bh4[2]);
                mma16816(sfr[nb * 2 + 1], ql, bh4[1], bh4[3]);
            }
        }

        // ---- online softmax (SCALE folded into exp arg)
        float mt0 = m0, mt1 = m1;
#pragma unroll
        for (int j = 0; j < 8; j++) {
            mt0 = fmaxf(mt0, fmaxf(sfr[j][0], sfr[j][1]));
            mt1 = fmaxf(mt1, fmaxf(sfr[j][2], sfr[j][3]));
        }
        mt0 = fmaxf(mt0, __shfl_xor_sync(0xffffffffu, mt0, 1));
        mt0 = fmaxf(mt0, __shfl_xor_sync(0xffffffffu, mt0, 2));
        mt1 = fmaxf(mt1, __shfl_xor_sync(0xffffffffu, mt1, 1));
        mt1 = fmaxf(mt1, __shfl_xor_sync(0xffffffffu, mt1, 2));

        const float al0 = __expf((m0 - mt0) * SCALE);
        const float al1 = __expf((m1 - mt1) * SCALE);
        m0 = mt0; m1 = mt1;

        float rs0 = 0.0f, rs1 = 0.0f;
#pragma unroll
        for (int j = 0; j < 8; j++) {
            sfr[j][0] = __expf((sfr[j][0] - m0) * SCALE);
            sfr[j][1] = __expf((sfr[j][1] - m0) * SCALE);
            sfr[j][2] = __expf((sfr[j][2] - m1) * SCALE);
            sfr[j][3] = __expf((sfr[j][3] - m1) * SCALE);
            rs0 += sfr[j][0] + sfr[j][1];
            rs1 += sfr[j][2] + sfr[j][3];
        }
        rs0 += __shfl_xor_sync(0xffffffffu, rs0, 1);
        rs0 += __shfl_xor_sync(0xffffffffu, rs0, 2);
        rs1 += __shfl_xor_sync(0xffffffffu, rs1, 1);
        rs1 += __shfl_xor_sync(0xffffffffu, rs1, 2);
        l0 = l0 * al0 + rs0;
        l1 = l1 * al1 + rs1;
#pragma unroll
        for (int j = 0; j < 8; j++) {
            Oacc[j][0] *= al0;
            Oacc[j][1] *= al0;
            Oacc[j][2] *= al1;
            Oacc[j][3] *= al1;
        }

        // ---- O += P V
#pragma unroll
        for (int st = 0; st < 4; st++) {       // key k16 steps
            uint32_t pa_h[4], pa_l[4];
#pragma unroll
            for (int q = 0; q < 2; q++) {
                const float* f = sfr[2 * st + q];
#pragma unroll
                for (int hv = 0; hv < 2; hv++) {
                    float x = f[hv * 2], y = f[hv * 2 + 1];
                    __nv_bfloat16 hx = __float2bfloat16(x);
                    __nv_bfloat16 hy = __float2bfloat16(y);
                    pa_h[q * 2 + hv] =
                        packbf2(__bfloat162float(hx), __bfloat162float(hy));
                    pa_l[q * 2 + hv] =
                        packbf2(x - __bfloat162float(hx), y - __bfloat162float(hy));
                }
            }
#pragma unroll
            for (int nb = 0; nb < 4; nb++) {   // dk n16 blocks
                uint32_t vh4[4], vl4[4];
                ldm_x4_t(vh4, fragT<AROW>(vHi, st * 16, nb * 32, lane));
                ldm_x4_t(vl4, fragT<AROW>(vLo, st * 16, nb * 32, lane));
                mma16816(Oacc[nb * 2 + 0], pa_h, vh4[0], vh4[2]);
                mma16816(Oacc[nb * 2 + 1], pa_h, vh4[1], vh4[3]);
                mma16816(Oacc[nb * 2 + 0], pa_h, vl4[0], vl4[2]);
                mma16816(Oacc[nb * 2 + 1], pa_h, vl4[1], vl4[3]);
                mma16816(Oacc[nb * 2 + 0], pa_l, vh4[0], vh4[2]);
                mma16816(Oacc[nb * 2 + 1], pa_l, vh4[1], vh4[3]);
            }
        }
        __syncthreads();
    }

    // ---- epilogue: normalize, split to bf16 hi/lo, write [B,S,D]
    const float inv0 = 1.0f / l0;
    const float inv1 = 1.0f / l1;
    const int g = lane >> 2;
    const int t = lane & 3;
    const int row0 = qt * 128 + w * 16 + g;
    const size_t gbase0 = ((size_t)b * Ss + row0) * Dd + h * 64;
    const size_t gbase1 = gbase0 + 8 * Dd;
#pragma unroll
    for (int j = 0; j < 8; j++) {
        int col = j * 8 + t * 2;
        float o00 = Oacc[j][0] * inv0, o01 = Oacc[j][1] * inv0;
        float o10 = Oacc[j][2] * inv1, o11 = Oacc[j][3] * inv1;
        __nv_bfloat16 h00 = __float2bfloat16(o00), h01 = __float2bfloat16(o01);
        __nv_bfloat16 h10 = __float2bfloat16(o10), h11 = __float2bfloat16(o11);
        *(uint32_t*)(g_ohi + gbase0 + col) =
            packbf2(__bfloat162float(h00), __bfloat162float(h01));
        *(uint32_t*)(g_olo + gbase0 + col) =
            packbf2(o00 - __bfloat162float(h00), o01 - __bfloat162float(h01));
        *(uint32_t*)(g_ohi + gbase1 + col) =
            packbf2(__bfloat162float(h10), __bfloat162float(h11));
        *(uint32_t*)(g_olo + gbase1 + col) =
            packbf2(o10 - __bfloat162float(h10), o11 - __bfloat162float(h11));
    }
}

// ---------------------------------------------------------------------------
// Launch
// ---------------------------------------------------------------------------
extern "C" void kernel_launch(void* const* d_in, const int* in_sizes, int n_in,
                              void* d_out, int out_size) {
    const float* q  = (const float*)d_in[0];
    const float* k  = (const float*)d_in[1];
    const float* v  = (const float*)d_in[2];
    const float* Wq = (const float*)d_in[3];
    const float* Wk = (const float*)d_in[4];
    const float* Wv = (const float*)d_in[5];
    const float* Wo = (const float*)d_in[6];
    float* out = (float*)d_out;

    __nv_bfloat16 *qhi, *qlo, *khi, *klo, *vhi, *vlo, *ohi, *olo, *whi, *wlo;
    __nv_bfloat16 *Qh, *Ql, *Kh, *Kl, *Vh, *Vl;
    cudaGetSymbolAddress((void**)&qhi, g_qhi);
    cudaGetSymbolAddress((void**)&qlo, g_qlo);
    cudaGetSymbolAddress((void**)&khi, g_khi);
    cudaGetSymbolAddress((void**)&klo, g_klo);
    cudaGetSymbolAddress((void**)&vhi, g_vhi);
    cudaGetSymbolAddress((void**)&vlo, g_vlo);
    cudaGetSymbolAddress((void**)&ohi, g_ohi);
    cudaGetSymbolAddress((void**)&olo, g_olo);
    cudaGetSymbolAddress((void**)&whi, g_whi);
    cudaGetSymbolAddress((void**)&wlo, g_wlo);
    cudaGetSymbolAddress((void**)&Qh, g_Qh);
    cudaGetSymbolAddress((void**)&Ql, g_Ql);
    cudaGetSymbolAddress((void**)&Kh, g_Kh);
    cudaGetSymbolAddress((void**)&Kl, g_Kl);
    cudaGetSymbolAddress((void**)&Vh, g_Vh);
    cudaGetSymbolAddress((void**)&Vl, g_Vl);
    const size_t WSTRIDE = (size_t)Dd * Dd;

    cudaFuncSetAttribute(attn_mma,
                         cudaFuncAttributeMaxDynamicSharedMemorySize, ATT_SMEM);
    cudaFuncSetAttribute(gemm_bf16split<0>,
                         cudaFuncAttributeMaxDynamicSharedMemorySize, GEMM_SMEM_BYTES);
    cudaFuncSetAttribute(gemm_bf16split<2>,
                         cudaFuncAttributeMaxDynamicSharedMemorySize, GEMM_SMEM_BYTES);

    const int cvt_blocks = Mrows * Dd / (256 * 4);
    cvt_split<<<cvt_blocks, 256>>>(q, qhi, qlo);
    cvt_split<<<cvt_blocks, 256>>>(k, khi, klo);
    cvt_split<<<cvt_blocks, 256>>>(v, vhi, vlo);

    dim3 tB(32, 8), tG(Dd / 32, Dd / 32);
    cvt_splitT<<<tG, tB>>>(Wq, whi + 0 * WSTRIDE, wlo + 0 * WSTRIDE);
    cvt_splitT<<<tG, tB>>>(Wk, whi + 1 * WSTRIDE, wlo + 1 * WSTRIDE);
    cvt_splitT<<<tG, tB>>>(Wv, whi + 2 * WSTRIDE, wlo + 2 * WSTRIDE);
    cvt_splitT<<<tG, tB>>>(Wo, whi + 3 * WSTRIDE, wlo + 3 * WSTRIDE);

    dim3 gg(Dd / 128, Mrows / 128);
    gemm_bf16split<2><<<gg, 256, GEMM_SMEM_BYTES>>>(
        qhi, qlo, whi + 0 * WSTRIDE, wlo + 0 * WSTRIDE, nullptr, Qh, Ql);
    gemm_bf16split<2><<<gg, 256, GEMM_SMEM_BYTES>>>(
        khi, klo, whi + 1 * WSTRIDE, wlo + 1 * WSTRIDE, nullptr, Kh, Kl);
    gemm_bf16split<2><<<gg, 256, GEMM_SMEM_BYTES>>>(
        vhi, vlo, whi + 2 * WSTRIDE, wlo + 2 * WSTRIDE, nullptr, Vh, Vl);

    attn_mma<<<dim3(Ss / 128, Bb * Hh), 256, ATT_SMEM>>>();

    gemm_bf16split<0><<<gg, 256, GEMM_SMEM_BYTES>>>(
        ohi, olo, whi + 3 * WSTRIDE, wlo + 3 * WSTRIDE, out, nullptr, nullptr);
}

// round 7
// speedup vs baseline: 1.0925x; 1.0925x over previous
#include <cuda_runtime.h>
#include <cuda_bf16.h>
#include <cuda_fp16.h>
#include <cstdint>
#include <math.h>

// ---------------------------------------------------------------------------
// Problem constants
// ---------------------------------------------------------------------------
constexpr int Bb = 2;
constexpr int Ss = 2048;
constexpr int Dd = 1024;
constexpr int Hh = 16;
constexpr int DK = 64;
constexpr int Mrows = Bb * Ss;           // 4096
constexpr float CEXP = 0.18033688f;      // (1/sqrt(64)) * log2(e)

// ---------------------------------------------------------------------------
// Scratch (device globals)
// ---------------------------------------------------------------------------
__device__ __nv_bfloat16 g_qhi[(size_t)Mrows * Dd], g_qlo[(size_t)Mrows * Dd];
__device__ __nv_bfloat16 g_khi[(size_t)Mrows * Dd], g_klo[(size_t)Mrows * Dd];
__device__ __nv_bfloat16 g_vhi[(size_t)Mrows * Dd], g_vlo[(size_t)Mrows * Dd];
__device__ __nv_bfloat16 g_ohi[(size_t)Mrows * Dd], g_olo[(size_t)Mrows * Dd];
__device__ __nv_bfloat16 g_whi[4][(size_t)Dd * Dd], g_wlo[4][(size_t)Dd * Dd];

// split-head projected tensors [bh=32][S=2048][DK=64]
__device__ __nv_bfloat16 g_Qh[(size_t)32 * Ss * DK], g_Ql[(size_t)32 * Ss * DK];
__device__ __nv_bfloat16 g_Kh[(size_t)32 * Ss * DK], g_Kl[(size_t)32 * Ss * DK];
__device__ __half        g_Vh[(size_t)32 * Ss * DK], g_Vl[(size_t)32 * Ss * DK];

// ---------------------------------------------------------------------------
// mma.sync / ldmatrix / cp.async helpers
// ---------------------------------------------------------------------------
__device__ __forceinline__ uint32_t smem_u32(const void* p) {
    uint32_t a;
    asm("{ .reg .u64 t; cvta.to.shared.u64 t, %1; cvt.u32.u64 %0, t; }"
        : "=r"(a) : "l"(p));
    return a;
}
__device__ __forceinline__ void ldm_x4(uint32_t* r, uint32_t addr) {
    asm volatile("ldmatrix.sync.aligned.m8n8.x4.shared.b16 {%0,%1,%2,%3}, [%4];"
                 : "=r"(r[0]), "=r"(r[1]), "=r"(r[2]), "=r"(r[3]) : "r"(addr));
}
__device__ __forceinline__ void ldm_x4_t(uint32_t* r, uint32_t addr) {
    asm volatile("ldmatrix.sync.aligned.m8n8.x4.trans.shared.b16 {%0,%1,%2,%3}, [%4];"
                 : "=r"(r[0]), "=r"(r[1]), "=r"(r[2]), "=r"(r[3]) : "r"(addr));
}
__device__ __forceinline__ void mma16816(float* c, const uint32_t* a,
                                         uint32_t b0, uint32_t b1) {
    asm volatile(
        "mma.sync.aligned.m16n8k16.row.col.f32.bf16.bf16.f32 "
        "{%0,%1,%2,%3}, {%4,%5,%6,%7}, {%8,%9}, {%0,%1,%2,%3};"
        : "+f"(c[0]), "+f"(c[1]), "+f"(c[2]), "+f"(c[3])
        : "r"(a[0]), "r"(a[1]), "r"(a[2]), "r"(a[3]), "r"(b0), "r"(b1));
}
__device__ __forceinline__ void mma16816h(float* c, const uint32_t* a,
                                          uint32_t b0, uint32_t b1) {
    asm volatile(
        "mma.sync.aligned.m16n8k16.row.col.f32.f16.f16.f32 "
        "{%0,%1,%2,%3}, {%4,%5,%6,%7}, {%8,%9}, {%0,%1,%2,%3};"
        : "+f"(c[0]), "+f"(c[1]), "+f"(c[2]), "+f"(c[3])
        : "r"(a[0]), "r"(a[1]), "r"(a[2]), "r"(a[3]), "r"(b0), "r"(b1));
}
__device__ __forceinline__ void cp16(uint32_t dst, const void* src) {
    asm volatile("cp.async.cg.shared.global [%0], [%1], 16;"
                 :: "r"(dst), "l"(src) : "memory");
}
__device__ __forceinline__ void cp_commit() {
    asm volatile("cp.async.commit_group;" ::: "memory");
}
template <int N>
__device__ __forceinline__ void cp_wait() {
    asm volatile("cp.async.wait_group %0;" :: "n"(N) : "memory");
}
template <int ROWB>
__device__ __forceinline__ uint32_t fragA(uint32_t base, int row0, int kb0, int lane) {
    int r = row0 + ((lane >> 3) & 1) * 8 + (lane & 7);
    int kb = kb0 + (lane >> 4) * 16;
    return base + r * ROWB + kb;
}
template <int ROWB>
__device__ __forceinline__ uint32_t fragT(uint32_t base, int k0, int nb0, int lane) {
    int r = k0 + ((lane >> 4) & 1) * 8 + (lane & 7);
    int cb = nb0 + ((lane >> 3) & 1) * 16;
    return base + r * ROWB + cb;
}
__device__ __forceinline__ uint32_t packbf2(float lo, float hi) {
    __nv_bfloat162 t = __floats2bfloat162_rn(lo, hi);
    return *(uint32_t*)&t;
}
__device__ __forceinline__ uint32_t packh2(float lo, float hi) {
    uint32_t r;
    asm("cvt.rn.f16x2.f32 %0, %1, %2;" : "=r"(r) : "f"(hi), "f"(lo));
    return r;
}
__device__ __forceinline__ uint32_t ex2h2(uint32_t x) {
    uint32_t r;
    asm("ex2.approx.f16x2 %0, %1;" : "=r"(r) : "r"(x));
    return r;
}
__device__ __forceinline__ float ex2f(float x) {
    float r;
    asm("ex2.approx.f32 %0, %1;" : "=f"(r) : "f"(x));
    return r;
}

// ---------------------------------------------------------------------------
// fp32 -> bf16 hi/lo split, row-major
// ---------------------------------------------------------------------------
__global__ __launch_bounds__(256)
void cvt_split(const float* __restrict__ x, __nv_bfloat16* __restrict__ hi,
               __nv_bfloat16* __restrict__ lo) {
    int i = (blockIdx.x * 256 + threadIdx.x) * 4;
    float4 v = *(const float4*)(x + i);
    float vv[4] = {v.x, v.y, v.z, v.w};
#pragma unroll
    for (int j = 0; j < 4; j++) {
        __nv_bfloat16 h = __float2bfloat16(vv[j]);
        hi[i + j] = h;
        lo[i + j] = __float2bfloat16(vv[j] - __bfloat162float(h));
    }
}

// fp32 W[K,N] -> bf16 hi/lo TRANSPOSED [N,K]
__global__ __launch_bounds__(256)
void cvt_splitT(const float* __restrict__ W, __nv_bfloat16* __restrict__ hiT,
                __nv_bfloat16* __restrict__ loT) {
    __shared__ float t[32][33];
    int tx = threadIdx.x, ty = threadIdx.y;
    int n0 = blockIdx.x * 32, k0 = blockIdx.y * 32;
#pragma unroll
    for (int r = 0; r < 4; r++)
        t[ty + r * 8][tx] = W[(size_t)(k0 + ty + r * 8) * Dd + n0 + tx];
    __syncthreads();
#pragma unroll
    for (int r = 0; r < 4; r++) {
        int n = n0 + ty + r * 8;
        int k = k0 + tx;
        float x = t[tx][ty + r * 8];
        __nv_bfloat16 h = __float2bfloat16(x);
        hiT[(size_t)n * Dd + k] = h;
        loT[(size_t)n * Dd + k] = __float2bfloat16(x - __bfloat162float(h));
    }
}

// ---------------------------------------------------------------------------
// bf16-split tensor-core GEMM.
// MODE 0: fp32 row-major C.
// MODE 2: bf16 hi/lo split-head (Q,K).  MODE 3: fp16 hi/lo split-head (V).
// ---------------------------------------------------------------------------
constexpr int ROW_B = 80;
constexpr int ARR_B = 128 * ROW_B;
constexpr int BUF_B = 4 * ARR_B;
constexpr int GEMM_SMEM_BYTES = 2 * BUF_B;  // 81920

template <int MODE>
__global__ __launch_bounds__(256, 1)
void gemm_bf16split(const __nv_bfloat16* __restrict__ Ahi,
                    const __nv_bfloat16* __restrict__ Alo,
                    const __nv_bfloat16* __restrict__ Bhi,
                    const __nv_bfloat16* __restrict__ Blo,
                    float* __restrict__ C,
                    void* __restrict__ Chi_,
                    void* __restrict__ Clo_) {
    extern __shared__ char smem[];
    const uint32_t sbase = smem_u32(smem);
    const int tid = threadIdx.x;
    const int lane = tid & 31;
    const int wid = tid >> 5;
    const int wm = wid >> 2;
    const int wn = wid & 3;
    const int bm = blockIdx.y * 128;
    const int bn = blockIdx.x * 128;

    const __nv_bfloat16* srcs[4] = {Ahi, Alo, Bhi, Blo};

    auto load_chunk = [&](int c, int b) {
        const int k0 = c * 32;
        const uint32_t dst0 = sbase + b * BUF_B;
        const int row = tid >> 1;
#pragma unroll
        for (int a4 = 0; a4 < 4; a4++) {
            const __nv_bfloat16* src = srcs[a4];
            const int rbase = (a4 < 2) ? bm : bn;
            const __nv_bfloat16* gsrc = src + (size_t)(rbase + row) * Dd + k0;
#pragma unroll
            for (int j = 0; j < 2; j++) {
                int cch = (tid & 1) * 2 + j;
                cp16(dst0 + a4 * ARR_B + row * ROW_B + cch * 16, gsrc + cch * 8);
            }
        }
        cp_commit();
    };

    float acc[4][4][4];
#pragma unroll
    for (int i = 0; i < 4; i++)
#pragma unroll
        for (int j = 0; j < 4; j++)
#pragma unroll
            for (int r = 0; r < 4; r++) acc[i][j][r] = 0.0f;

    auto compute = [&](int b) {
        const uint32_t base = sbase + b * BUF_B;
        const uint32_t aHiB = base + 0 * ARR_B;
        const uint32_t aLoB = base + 1 * ARR_B;
        const uint32_t bHiB = base + 2 * ARR_B;
        const uint32_t bLoB = base + 3 * ARR_B;
#pragma unroll
        for (int s = 0; s < 2; s++) {
            const int kb = s * 32;
            uint32_t ahi[4][4], alo[4][4];
#pragma unroll
            for (int i = 0; i < 4; i++) {
                ldm_x4(ahi[i], fragA<ROW_B>(aHiB, wm * 64 + i * 16, kb, lane));
                ldm_x4(alo[i], fragA<ROW_B>(aLoB, wm * 64 + i * 16, kb, lane));
            }
#pragma unroll
            for (int nb = 0; nb < 2; nb++) {
                uint32_t bh[4], bl[4];
                ldm_x4(bh, fragA<ROW_B>(bHiB, wn * 32 + nb * 16, kb, lane));
                ldm_x4(bl, fragA<ROW_B>(bLoB, wn * 32 + nb * 16, kb, lane));
#pragma unroll
                for (int i = 0; i < 4; i++) {
                    mma16816(acc[i][nb * 2 + 0], ahi[i], bh[0], bh[2]);
                    mma16816(acc[i][nb * 2 + 1], ahi[i], bh[1], bh[3]);
                    mma16816(acc[i][nb * 2 + 0], ahi[i], bl[0], bl[2]);
                    mma16816(acc[i][nb * 2 + 1], ahi[i], bl[1], bl[3]);
                    mma16816(acc[i][nb * 2 + 0], alo[i], bh[0], bh[2]);
                    mma16816(acc[i][nb * 2 + 1], alo[i], bh[1], bh[3]);
                }
            }
        }
    };

    constexpr int NCHUNK = Dd / 32;
    load_chunk(0, 0);
    for (int c = 0; c < NCHUNK; c++) {
        if (c + 1 < NCHUNK) {
            load_chunk(c + 1, (c + 1) & 1);
            cp_wait<1>();
        } else {
            cp_wait<0>();
        }
        __syncthreads();
        compute(c & 1);
        __syncthreads();
    }

    const int g = lane >> 2;
    const int tg = lane & 3;
#pragma unroll
    for (int i = 0; i < 4; i++) {
        int r0 = bm + wm * 64 + i * 16 + g;
#pragma unroll
        for (int j = 0; j < 4; j++) {
            int col = bn + wn * 32 + j * 8 + tg * 2;
            if (MODE == 0) {
                *(float2*)(C + (size_t)r0 * Dd + col) =
                    make_float2(acc[i][j][0], acc[i][j][1]);
                *(float2*)(C + (size_t)(r0 + 8) * Dd + col) =
                    make_float2(acc[i][j][2], acc[i][j][3]);
            } else {
                int h = col >> 6, dk = col & 63;
#pragma unroll
                for (int half = 0; half < 2; half++) {
                    int r = r0 + half * 8;
                    int b_ = r >> 11, s = r & 2047;
                    size_t addr = (((size_t)(b_ * Hh + h)) * Ss + s) * DK + dk;
                    float x = acc[i][j][half * 2], y = acc[i][j][half * 2 + 1];
                    if (MODE == 2) {
                        __nv_bfloat16* Chi = (__nv_bfloat16*)Chi_;
                        __nv_bfloat16* Clo = (__nv_bfloat16*)Clo_;
                        __nv_bfloat16 hx = __float2bfloat16(x);
                        __nv_bfloat16 hy = __float2bfloat16(y);
                        *(uint32_t*)(Chi + addr) =
                            packbf2(__bfloat162float(hx), __bfloat162float(hy));
                        *(uint32_t*)(Clo + addr) =
                            packbf2(x - __bfloat162float(hx), y - __bfloat162float(hy));
                    } else {
                        __half* Chi = (__half*)Chi_;
                        __half* Clo = (__half*)Clo_;
                        __half hx = __float2half_rn(x);
                        __half hy = __float2half_rn(y);
                        *(uint32_t*)(Chi + addr) =
                            packh2(__half2float(hx), __half2float(hy));
                        *(uint32_t*)(Clo + addr) =
                            packh2(x - __half2float(hx), y - __half2float(hy));
                    }
                }
            }
        }
    }
}

// ---------------------------------------------------------------------------
// Tensor-core flash attention, 64-key tiles.
// QK: bf16 3-product.  Softmax: ex2.approx.f16x2 (P packed fp16 directly).
// PV: fp16 MMA, P*Vhi + P*Vlo (2 products).
// ---------------------------------------------------------------------------
constexpr int AROW = 144;
constexpr int Q_TILE_B = 128 * AROW;             // 18432
constexpr int KV_TILE_B = 64 * AROW;             // 9216
constexpr int ATT_BUF_B = 4 * KV_TILE_B;         // 36864
constexpr int ATT_SMEM = 2 * Q_TILE_B + 2 * ATT_BUF_B;  // 110592

__global__ __launch_bounds__(256, 2)
void attn_mma() {
    extern __shared__ char smem[];
    const uint32_t sb = smem_u32(smem);
    const int tid = threadIdx.x;
    const int lane = tid & 31;
    const int w = tid >> 5;
    const int bh = blockIdx.y;
    const int qt = blockIdx.x;
    const int b = bh >> 4, h = bh & 15;

    const __nv_bfloat16* Qhg = g_Qh + (size_t)bh * Ss * DK + qt * 128 * DK;
    const __nv_bfloat16* Qlg = g_Ql + (size_t)bh * Ss * DK + qt * 128 * DK;
    const __nv_bfloat16* Khg = g_Kh + (size_t)bh * Ss * DK;
    const __nv_bfloat16* Klg = g_Kl + (size_t)bh * Ss * DK;
    const __half* Vhg = g_Vh + (size_t)bh * Ss * DK;
    const __half* Vlg = g_Vl + (size_t)bh * Ss * DK;

    const uint32_t sQh = sb, sQl = sb + Q_TILE_B;

    auto load_kv = [&](int kt, int buf) {
        const uint32_t base = sb + 2 * Q_TILE_B + buf * ATT_BUF_B;
        const void* gk[4] = {Khg, Klg, Vhg, Vlg};
#pragma unroll
        for (int a4 = 0; a4 < 4; a4++) {
            const char* src = (const char*)gk[a4] + (size_t)kt * 64 * DK * 2;
#pragma unroll
            for (int p = 0; p < 2; p++) {
                int idx = tid + p * 256;
                int r = idx >> 3, c = idx & 7;
                cp16(base + a4 * KV_TILE_B + r * AROW + c * 16,
                     src + (r * DK + c * 8) * 2);
            }
        }
        cp_commit();
    };

#pragma unroll
    for (int p = 0; p < 4; p++) {
        int idx = tid + p * 256;
        int r = idx >> 3, c = idx & 7;
        cp16(sQh + r * AROW + c * 16, Qhg + r * DK + c * 8);
        cp16(sQl + r * AROW + c * 16, Qlg + r * DK + c * 8);
    }
    load_kv(0, 0);
    cp_wait<0>();
    __syncthreads();

    float m0 = -1e30f, m1 = -1e30f, l0 = 0.0f, l1 = 0.0f;
    float Oacc[8][4];
#pragma unroll
    for (int j = 0; j < 8; j++)
#pragma unroll
        for (int r = 0; r < 4; r++) Oacc[j][r] = 0.0f;

    constexpr int NT = Ss / 64;   // 32
    for (int kt = 0; kt < NT; kt++) {
        if (kt + 1 < NT) {
            load_kv(kt + 1, (kt + 1) & 1);
            cp_wait<1>();
        } else {
            cp_wait<0>();
        }
        __syncthreads();

        const uint32_t base = sb + 2 * Q_TILE_B + (kt & 1) * ATT_BUF_B;
        const uint32_t kHi = base, kLo = base + KV_TILE_B;
        const uint32_t vHi = base + 2 * KV_TILE_B, vLo = base + 3 * KV_TILE_B;

        // ---- S = Q K^T (fp32 acc), 16x64 per warp
        float sfr[8][4];
#pragma unroll
        for (int j = 0; j < 8; j++)
#pragma unroll
            for (int r = 0; r < 4; r++) sfr[j][r] = 0.0f;

#pragma unroll
        for (int s = 0; s < 4; s++) {
            const int kb = s * 32;
            uint32_t qh[4], ql[4];
            ldm_x4(qh, fragA<AROW>(sQh, w * 16, kb, lane));
            ldm_x4(ql, fragA<AROW>(sQl, w * 16, kb, lane));
#pragma unroll
            for (int nb = 0; nb < 4; nb++) {
                uint32_t bh4[4], bl4[4];
                ldm_x4(bh4, fragA<AROW>(kHi, nb * 16, kb, lane));
                ldm_x4(bl4, fragA<AROW>(kLo, nb * 16, kb, lane));
                mma16816(sfr[nb * 2 + 0], qh, bh4[0], bh4[2]);
                mma16816(sfr[nb * 2 + 1], qh, bh4[1], bh4[3]);
                mma16816(sfr[nb * 2 + 0], qh, bl4[0], bl4[2]);
                mma16816(sfr[nb * 2 + 1], qh, bl4[1], bl4[3]);
                mma16816(sfr[nb * 2 + 0], ql, bh4[0], bh4[2]);
                mma16816(sfr[nb * 2 + 1], ql, bh4[1], bh4[3]);
            }
        }

        // ---- online softmax: P = 2^((S - m)*CEXP) computed in f16x2
        float mt0 = m0, mt1 = m1;
#pragma unroll
        for (int j = 0; j < 8; j++) {
            mt0 = fmaxf(mt0, fmaxf(sfr[j][0], sfr[j][1]));
            mt1 = fmaxf(mt1, fmaxf(sfr[j][2], sfr[j][3]));
        }
        mt0 = fmaxf(mt0, __shfl_xor_sync(0xffffffffu, mt0, 1));
        mt0 = fmaxf(mt0, __shfl_xor_sync(0xffffffffu, mt0, 2));
        mt1 = fmaxf(mt1, __shfl_xor_sync(0xffffffffu, mt1, 1));
        mt1 = fmaxf(mt1, __shfl_xor_sync(0xffffffffu, mt1, 2));

        const float al0 = ex2f((m0 - mt0) * CEXP);
        const float al1 = ex2f((m1 - mt1) * CEXP);
        m0 = mt0; m1 = mt1;
        const float mc0 = m0 * CEXP, mc1 = m1 * CEXP;

        uint32_t p2[8][2];
#pragma unroll
        for (int j = 0; j < 8; j++) {
            uint32_t t0 = packh2(fmaf(sfr[j][0], CEXP, -mc0),
                                 fmaf(sfr[j][1], CEXP, -mc0));
            uint32_t t1 = packh2(fmaf(sfr[j][2], CEXP, -mc1),
                                 fmaf(sfr[j][3], CEXP, -mc1));
            p2[j][0] = ex2h2(t0);
            p2[j][1] = ex2h2(t1);
        }

        // row sums: pairwise HADD2 tree, unpack once
        __half2 s0a = __hadd2(*(__half2*)&p2[0][0], *(__half2*)&p2[1][0]);
        __half2 s0b = __hadd2(*(__half2*)&p2[2][0], *(__half2*)&p2[3][0]);
        __half2 s0c = __hadd2(*(__half2*)&p2[4][0], *(__half2*)&p2[5][0]);
        __half2 s0d = __hadd2(*(__half2*)&p2[6][0], *(__half2*)&p2[7][0]);
        __half2 s0 = __hadd2(__hadd2(s0a, s0b), __hadd2(s0c, s0d));
        __half2 s1a = __hadd2(*(__half2*)&p2[0][1], *(__half2*)&p2[1][1]);
        __half2 s1b = __hadd2(*(__half2*)&p2[2][1], *(__half2*)&p2[3][1]);
        __half2 s1c = __hadd2(*(__half2*)&p2[4][1], *(__half2*)&p2[5][1]);
        __half2 s1d = __hadd2(*(__half2*)&p2[6][1], *(__half2*)&p2[7][1]);
        __half2 s1 = __hadd2(__hadd2(s1a, s1b), __hadd2(s1c, s1d));
        float2 f0 = __half22float2(s0);
        float2 f1 = __half22float2(s1);
        float rs0 = f0.x + f0.y;
        float rs1 = f1.x + f1.y;
        rs0 += __shfl_xor_sync(0xffffffffu, rs0, 1);
        rs0 += __shfl_xor_sync(0xffffffffu, rs0, 2);
        rs1 += __shfl_xor_sync(0xffffffffu, rs1, 1);
        rs1 += __shfl_xor_sync(0xffffffffu, rs1, 2);
        l0 = l0 * al0 + rs0;
        l1 = l1 * al1 + rs1;
#pragma unroll
        for (int j = 0; j < 8; j++) {
            Oacc[j][0] *= al0;
            Oacc[j][1] *= al0;
            Oacc[j][2] *= al1;
            Oacc[j][3] *= al1;
        }

        // ---- O += P V  (fp16 MMA, 2 products)
#pragma unroll
        for (int st = 0; st < 4; st++) {
            uint32_t pa[4] = {p2[2 * st][0], p2[2 * st][1],
                              p2[2 * st + 1][0], p2[2 * st + 1][1]};
#pragma unroll
            for (int nb = 0; nb < 4; nb++) {
                uint32_t vh4[4], vl4[4];
                ldm_x4_t(vh4, fragT<AROW>(vHi, st * 16, nb * 32, lane));
                ldm_x4_t(vl4, fragT<AROW>(vLo, st * 16, nb * 32, lane));
                mma16816h(Oacc[nb * 2 + 0], pa, vh4[0], vh4[2]);
                mma16816h(Oacc[nb * 2 + 1], pa, vh4[1], vh4[3]);
                mma16816h(Oacc[nb * 2 + 0], pa, vl4[0], vl4[2]);
                mma16816h(Oacc[nb * 2 + 1], pa, vl4[1], vl4[3]);
            }
        }
        __syncthreads();
    }

    // ---- epilogue: normalize, split to bf16 hi/lo, write [B,S,D]
    const float inv0 = 1.0f / l0;
    const float inv1 = 1.0f / l1;
    const int g = lane >> 2;
    const int t = lane & 3;
    const int row0 = qt * 128 + w * 16 + g;
    const size_t gbase0 = ((size_t)b * Ss + row0) * Dd + h * 64;
    const size_t gbase1 = gbase0 + 8 * Dd;
#pragma unroll
    for (int j = 0; j < 8; j++) {
        int col = j * 8 + t * 2;
        float o00 = Oacc[j][0] * inv0, o01 = Oacc[j][1] * inv0;
        float o10 = Oacc[j][2] * inv1, o11 = Oacc[j][3] * inv1;
        __nv_bfloat16 h00 = __float2bfloat16(o00), h01 = __float2bfloat16(o01);
        __nv_bfloat16 h10 = __float2bfloat16(o10), h11 = __float2bfloat16(o11);
        *(uint32_t*)(g_ohi + gbase0 + col) =
            packbf2(__bfloat162float(h00), __bfloat162float(h01));
        *(uint32_t*)(g_olo + gbase0 + col) =
            packbf2(o00 - __bfloat162float(h00), o01 - __bfloat162float(h01));
        *(uint32_t*)(g_ohi + gbase1 + col) =
            packbf2(__bfloat162float(h10), __bfloat162float(h11));
        *(uint32_t*)(g_olo + gbase1 + col) =
            packbf2(o10 - __bfloat162float(h10), o11 - __bfloat162float(h11));
    }
}

// ---------------------------------------------------------------------------
// Launch
// ---------------------------------------------------------------------------
extern "C" void kernel_launch(void* const* d_in, const int* in_sizes, int n_in,
                              void* d_out, int out_size) {
    const float* q  = (const float*)d_in[0];
    const float* k  = (const float*)d_in[1];
    const float* v  = (const float*)d_in[2];
    const float* Wq = (const float*)d_in[3];
    const float* Wk = (const float*)d_in[4];
    const float* Wv = (const float*)d_in[5];
    const float* Wo = (const float*)d_in[6];
    float* out = (float*)d_out;

    __nv_bfloat16 *qhi, *qlo, *khi, *klo, *vhi, *vlo, *ohi, *olo, *whi, *wlo;
    __nv_bfloat16 *Qh, *Ql, *Kh, *Kl;
    __half *Vh, *Vl;
    cudaGetSymbolAddress((void**)&qhi, g_qhi);
    cudaGetSymbolAddress((void**)&qlo, g_qlo);
    cudaGetSymbolAddress((void**)&khi, g_khi);
    cudaGetSymbolAddress((void**)&klo, g_klo);
    cudaGetSymbolAddress((void**)&vhi, g_vhi);
    cudaGetSymbolAddress((void**)&vlo, g_vlo);
    cudaGetSymbolAddress((void**)&ohi, g_ohi);
    cudaGetSymbolAddress((void**)&olo, g_olo);
    cudaGetSymbolAddress((void**)&whi, g_whi);
    cudaGetSymbolAddress((void**)&wlo, g_wlo);
    cudaGetSymbolAddress((void**)&Qh, g_Qh);
    cudaGetSymbolAddress((void**)&Ql, g_Ql);
    cudaGetSymbolAddress((void**)&Kh, g_Kh);
    cudaGetSymbolAddress((void**)&Kl, g_Kl);
    cudaGetSymbolAddress((void**)&Vh, g_Vh);
    cudaGetSymbolAddress((void**)&Vl, g_Vl);
    const size_t WSTRIDE = (size_t)Dd * Dd;

    cudaFuncSetAttribute(attn_mma,
                         cudaFuncAttributeMaxDynamicSharedMemorySize, ATT_SMEM);
    cudaFuncSetAttribute(gemm_bf16split<0>,
                         cudaFuncAttributeMaxDynamicSharedMemorySize, GEMM_SMEM_BYTES);
    cudaFuncSetAttribute(gemm_bf16split<2>,
                         cudaFuncAttributeMaxDynamicSharedMemorySize, GEMM_SMEM_BYTES);
    cudaFuncSetAttribute(gemm_bf16split<3>,
                         cudaFuncAttributeMaxDynamicSharedMemorySize, GEMM_SMEM_BYTES);

    const int cvt_blocks = Mrows * Dd / (256 * 4);
    cvt_split<<<cvt_blocks, 256>>>(q, qhi, qlo);
    cvt_split<<<cvt_blocks, 256>>>(k, khi, klo);
    cvt_split<<<cvt_blocks, 256>>>(v, vhi, vlo);

    dim3 tB(32, 8), tG(Dd / 32, Dd / 32);
    cvt_splitT<<<tG, tB>>>(Wq, whi + 0 * WSTRIDE, wlo + 0 * WSTRIDE);
    cvt_splitT<<<tG, tB>>>(Wk, whi + 1 * WSTRIDE, wlo + 1 * WSTRIDE);
    cvt_splitT<<<tG, tB>>>(Wv, whi + 2 * WSTRIDE, wlo + 2 * WSTRIDE);
    cvt_splitT<<<tG, tB>>>(Wo, whi + 3 * WSTRIDE, wlo + 3 * WSTRIDE);

    dim3 gg(Dd / 128, Mrows / 128);
    gemm_bf16split<2><<<gg, 256, GEMM_SMEM_BYTES>>>(
        qhi, qlo, whi + 0 * WSTRIDE, wlo + 0 * WSTRIDE, nullptr, Qh, Ql);
    gemm_bf16split<2><<<gg, 256, GEMM_SMEM_BYTES>>>(
        khi, klo, whi + 1 * WSTRIDE, wlo + 1 * WSTRIDE, nullptr, Kh, Kl);
    gemm_bf16split<3><<<gg, 256, GEMM_SMEM_BYTES>>>(
        vhi, vlo, whi + 2 * WSTRIDE, wlo + 2 * WSTRIDE, nullptr, Vh, Vl);

    attn_mma<<<dim3(Ss / 128, Bb * Hh), 256, ATT_SMEM>>>();

    gemm_bf16split<0><<<gg, 256, GEMM_SMEM_BYTES>>>(
        ohi, olo, whi + 3 * WSTRIDE, wlo + 3 * WSTRIDE, out, nullptr, nullptr);
}